// round 10
// baseline (speedup 1.0000x reference)
#include <cuda_runtime.h>
#include <cstdint>

// LSTM: B=2048, T=4096, I=5, H=10. Gate order i,f,g,o (rows of W_ih/W_hh).
//   gates = x @ W_ih^T + b_ih + b_hh + h @ W_hh^T
//   c = sigmoid(f)*c + sigmoid(i)*tanh(g);  h = sigmoid(o)*tanh(c)
//
// One thread per (batch, hidden unit j); 10-lane groups, 3 batches/warp.
// K-PAIR f32x2 packing: each gate accumulates over hidden-index pairs
// (h_{2m},h_{2m+1}) loaded directly from SMEM as b64 pairs (no duplication,
// no pack MOVs), one horizontal add per gate. Exchange = 1 STS.32 + syncwarp
// + 3 LDS, double-buffered. Branch-free output store (inactive lanes write a
// scratch sink). MUFU.TANH activations, sigmoid(x)=0.5+0.5*tanh(x/2) with
// the 0.5 folded into pre-scaled weights/biases.

#define BB 2048
#define TT 4096
#define II 5
#define HH 10

typedef unsigned long long u64;

__device__ float g_scratch[64];

static __device__ __forceinline__ u64 pk2(float a, float b) {
    u64 r;
    asm("mov.b64 %0, {%1, %2};" : "=l"(r) : "f"(a), "f"(b));
    return r;
}
static __device__ __forceinline__ void upk2(u64 v, float& a, float& b) {
    asm("mov.b64 {%0, %1}, %2;" : "=f"(a), "=f"(b) : "l"(v));
}
static __device__ __forceinline__ u64 ffma2(u64 a, u64 b, u64 c) {
    u64 d;
    asm("fma.rn.f32x2 %0, %1, %2, %3;" : "=l"(d) : "l"(a), "l"(b), "l"(c));
    return d;
}
// Single-MUFU tanh (MUFU.TANH), sm_75+.
static __device__ __forceinline__ float tanh_x(float x) {
    float y;
    asm("tanh.approx.f32 %0, %1;" : "=f"(y) : "f"(x));
    return y;
}

__global__ void __launch_bounds__(32)
lstm_scan_kernel(const float* __restrict__ x,
                 const float* __restrict__ h0,
                 const float* __restrict__ c0,
                 const float* __restrict__ W_ih,
                 const float* __restrict__ W_hh,
                 const float* __restrict__ b_ih,
                 const float* __restrict__ b_hh,
                 float* __restrict__ out)
{
    // Two 256B buffers. Per buffer: group g's 10 h floats at g*48 (40B used;
    // 48B stride keeps +16/+32 offsets 16/8-aligned), idle-lane sink at 144.
    __shared__ float sh[128];

    const int lane = threadIdx.x;
    const int group = (lane < 30) ? (lane / 10) : 0;
    const int j     = (lane < 30) ? (lane - group * 10) : 0;

    int b = blockIdx.x * 3 + group;
    const bool active = (lane < 30) && (b < BB);
    if (b >= BB) b = 0;  // clamp for safe (redundant) loads; store goes to sink

    const uint32_t shb = (uint32_t)__cvta_generic_to_shared(sh);
    const uint32_t lbase = shb + (uint32_t)(group * 48);
    const uint32_t sbase = shb + ((lane < 30) ? (uint32_t)(group * 48 + j * 4)
                                              : (uint32_t)(144 + (lane - 30) * 4));

    // Gate order f,i,g,o (f first: it heads the c -> tanh(c) -> h chain).
    const int   rows[4] = {HH + j, j, 2 * HH + j, 3 * HH + j};
    const float scs[4]  = {0.5f, 0.5f, 1.0f, 0.5f};

    u64 whh2[4][5], wih2[4][2];
    float w4[4], bias[4];
#pragma unroll
    for (int g = 0; g < 4; g++) {
        const int r = rows[g];
        const float s = scs[g];
#pragma unroll
        for (int m = 0; m < 5; m++)
            whh2[g][m] = pk2(s * W_hh[r * HH + 2 * m], s * W_hh[r * HH + 2 * m + 1]);
        wih2[g][0] = pk2(s * W_ih[r * II + 0], s * W_ih[r * II + 1]);
        wih2[g][1] = pk2(s * W_ih[r * II + 2], s * W_ih[r * II + 3]);
        w4[g]   = s * W_ih[r * II + 4];
        bias[g] = s * (b_ih[r] + b_hh[r]);
    }

    float h = h0[b * HH + j];
    float c = c0[b * HH + j];

    const float* xb = x + (size_t)b * TT * II;
    float* ob = active ? (out + (size_t)b * TT * HH + j) : (g_scratch + lane);
    const int ostep = active ? HH : 0;

    // Seed buffer 0 with h_0; loop's syncwarp orders it before the first LDS.
    asm volatile("st.shared.b32 [%0], %1;" :: "r"(sbase), "f"(h) : "memory");
    uint32_t buf = 0;

    // Prefetch x for t=0.
    float xn0 = xb[0], xn1 = xb[1], xn2 = xb[2], xn3 = xb[3], xn4 = xb[4];

#pragma unroll 2
    for (int t = 0; t < TT; ++t) {
        const float xc0 = xn0, xc1 = xn1, xc2 = xn2, xc3 = xn3, xc4 = xn4;

        // Prefetch next step's x (independent of the recurrent chain).
        {
            const int tn = (t + 1 < TT) ? (t + 1) : t;
            const float* xp = xb + tn * II;
            xn0 = xp[0]; xn1 = xp[1]; xn2 = xp[2]; xn3 = xp[3]; xn4 = xp[4];
        }

        // x contribution + scalar leftover + bias, folded into acc init.
        // lo half gets the scalar part so the final hadd is one FADD.
        const u64 xp01 = pk2(xc0, xc1);
        const u64 xp23 = pk2(xc2, xc3);
        u64 acc[4];
#pragma unroll
        for (int g = 0; g < 4; g++) {
            u64 a = pk2(fmaf(w4[g], xc4, bias[g]), 0.0f);
            a = ffma2(wih2[g][0], xp01, a);
            acc[g] = ffma2(wih2[g][1], xp23, a);
        }

        // ---- h exchange: previous iteration's STS -> sync -> 3 LDS ----
        __syncwarp();
        u64 p0, p1, p2, p3, p4;
        {
            const uint32_t lb = lbase + buf;
            asm volatile("ld.shared.v2.b64 {%0, %1}, [%2];"
                         : "=l"(p0), "=l"(p1) : "r"(lb) : "memory");
            asm volatile("ld.shared.v2.b64 {%0, %1}, [%2+16];"
                         : "=l"(p2), "=l"(p3) : "r"(lb) : "memory");
            asm volatile("ld.shared.b64 %0, [%1+32];"
                         : "=l"(p4) : "r"(lb) : "memory");
        }

        // Recurrent contribution over K-pairs (f gate first).
#pragma unroll
        for (int g = 0; g < 4; g++) {
            u64 a = acc[g];
            a = ffma2(whh2[g][0], p0, a);
            a = ffma2(whh2[g][1], p1, a);
            a = ffma2(whh2[g][2], p2, a);
            a = ffma2(whh2[g][3], p3, a);
            acc[g] = ffma2(whh2[g][4], p4, a);
        }

        // Horizontal add (lo already holds scalar part) + activations.
        float a0lo, a0hi, a1lo, a1hi, a2lo, a2hi, a3lo, a3hi;
        upk2(acc[0], a0lo, a0hi);
        upk2(acc[1], a1lo, a1hi);
        upk2(acc[2], a2lo, a2hi);
        upk2(acc[3], a3lo, a3hi);

        const float fg = fmaf(0.5f, tanh_x(a0lo + a0hi), 0.5f);
        const float ig = fmaf(0.5f, tanh_x(a1lo + a1hi), 0.5f);
        const float gg = tanh_x(a2lo + a2hi);
        const float og = fmaf(0.5f, tanh_x(a3lo + a3hi), 0.5f);

        c = fmaf(fg, c, ig * gg);
        h = og * tanh_x(c);

        // Publish h for next step into the other buffer; next syncwarp orders.
        asm volatile("st.shared.b32 [%0], %1;"
                     :: "r"(sbase + (buf ^ 256u)), "f"(h) : "memory");

        *ob = h;           // branch-free: inactive lanes hit the scratch sink
        ob += ostep;
        buf ^= 256u;
    }
}

extern "C" void kernel_launch(void* const* d_in, const int* in_sizes, int n_in,
                              void* d_out, int out_size) {
    (void)in_sizes; (void)n_in; (void)out_size;
    const float* x    = (const float*)d_in[0];
    const float* h0   = (const float*)d_in[1];
    const float* c0   = (const float*)d_in[2];
    const float* W_ih = (const float*)d_in[3];
    const float* W_hh = (const float*)d_in[4];
    const float* b_ih = (const float*)d_in[5];
    const float* b_hh = (const float*)d_in[6];
    float* out = (float*)d_out;

    const int nwarps = (BB + 2) / 3;  // 3 batches per warp
    lstm_scan_kernel<<<nwarps, 32>>>(x, h0, c0, W_ih, W_hh, b_ih, b_hh, out);
}